// round 10
// baseline (speedup 1.0000x reference)
#include <cuda_runtime.h>

// Fixed problem shapes
#define T_STEPS 5
#define BS      32
#define C       64
#define H       64
#define W       64
#define VTH     1.0f
// gamma = DROP_RATE / BLOCK_SIZE^2 = 0.1 / 49
#define GAMMA   0.002040816326530612f

#define N_PLANES (T_STEPS * BS)               // 160
#define PLANE    (H * W)                      // 4096
#define PLANE4   (PLANE / 4)                  // 1024
#define VEC_PER_T   2097152                   // BS*C*H*W/4
#define GRID_BLOCKS (VEC_PER_T / 256)         // 8192

#define MASK_BLOCKS 320                       // 160 planes x 2 halves
#define HALF_ROWS   32
#define HALO_ROWS   (HALF_ROWS + 6)           // 38
#define MAX_SEEDS   512                       // E[k] ~ 5 per half-plane halo

// dropblock keep-mask: [160, 64, 64] float (2.62 MB), static device mem
__device__ __align__(16) float d_bm[N_PLANES * PLANE];
// flag protocol (self-resetting each launch; zero-initialized)
__device__ int d_flag;
__device__ int d_done;

// ---------------------------------------------------------------------------
// Single fused kernel. Blocks 0..319 compute the mask (one half-plane each),
// then ALL blocks gate on d_flag==320 and run the lean LIF body.
// ---------------------------------------------------------------------------
__global__ void __launch_bounds__(256, 6)
fused_kernel(const float4* __restrict__ x,
             const float4* __restrict__ mr4,
             float4* __restrict__ out) {
    __shared__ int s_cnt;
    __shared__ int s_pts[MAX_SEEDS];   // packed (r << 8) | w

    const int bid = blockIdx.x;
    const int tid = threadIdx.x;
    const int v   = bid * 256 + tid;   // grid exactly covers VEC_PER_T

    // light x prefetch: keeps DRAM busy during mask/spin phase
    const float4 xt0 = x[v];
    const float4 xt1 = x[v + 1 * VEC_PER_T];

    // ---- mask phase (blocks 0..319 only) ----
    if (bid < MASK_BLOCKS) {
        const int n  = bid >> 1;                 // plane 0..159
        const int h0 = (bid & 1) * HALF_ROWS;    // 0 or 32
        if (tid == 0) s_cnt = 0;
        __syncthreads();

        // gather seeds from halo rows [h0-3, h0+34] clamped
        for (int i = tid; i < HALO_ROWS * 16; i += 256) {
            const int r = h0 - 3 + (i >> 4);
            if (r >= 0 && r < H) {
                const int qw = i & 15;
                const float4 mv = mr4[n * PLANE4 + r * 16 + qw];
                const int w0 = qw << 2;
                if (mv.x < GAMMA) { int s = atomicAdd(&s_cnt, 1); if (s < MAX_SEEDS) s_pts[s] = (r << 8) | (w0 + 0); }
                if (mv.y < GAMMA) { int s = atomicAdd(&s_cnt, 1); if (s < MAX_SEEDS) s_pts[s] = (r << 8) | (w0 + 1); }
                if (mv.z < GAMMA) { int s = atomicAdd(&s_cnt, 1); if (s < MAX_SEEDS) s_pts[s] = (r << 8) | (w0 + 2); }
                if (mv.w < GAMMA) { int s = atomicAdd(&s_cnt, 1); if (s < MAX_SEEDS) s_pts[s] = (r << 8) | (w0 + 3); }
            }
        }
        __syncthreads();

        const int k = (s_cnt < MAX_SEEDS) ? s_cnt : MAX_SEEDS;
        // emit 512 float4 (32 rows x 16) over 256 threads
        #pragma unroll
        for (int j = 0; j < 2; ++j) {
            const int idx = tid + j * 256;            // 0..511
            const int h   = h0 + (idx >> 4);
            const int wb  = (idx & 15) << 2;
            float4 m = make_float4(1.f, 1.f, 1.f, 1.f);
            for (int i = 0; i < k; ++i) {
                const int p  = s_pts[i];
                const int pr = p >> 8;
                if (abs(pr - h) <= 3) {
                    const int dw = (p & 255) - wb;
                    if (dw >= -3 && dw <= 3) m.x = 0.f;
                    if (dw >= -2 && dw <= 4) m.y = 0.f;
                    if (dw >= -1 && dw <= 5) m.z = 0.f;
                    if (dw >=  0 && dw <= 6) m.w = 0.f;
                }
            }
            reinterpret_cast<float4*>(d_bm)[n * PLANE4 + (h << 4) + (idx & 15)] = m;
        }

        __threadfence();          // publish this thread's d_bm stores
        __syncthreads();          // all threads of block published
        if (tid == 0) atomicAdd(&d_flag, 1);
    }

    // ---- gate: wait for all 320 mask blocks ----
    if (tid == 0) {
        while (*(volatile int*)&d_flag < MASK_BLOCKS) { __nanosleep(64); }
    }
    __syncthreads();
    __threadfence();              // acquire: order d_bm loads after flag observation

    // ---- LIF scan (lean R3 body) ----
    const int wq = v & 15;
    const int h  = (v >> 4) & 63;
    const int b  = v >> 16;
    const int bm_base = ((b << 6) + h) * 16 + wq;
    const float4* __restrict__ bm4 = reinterpret_cast<const float4*>(d_bm);

    float4 u = make_float4(0.f, 0.f, 0.f, 0.f);

    #define LIF_BODY(XT, BMT, T)                                             \
    {                                                                        \
        float4 o;                                                            \
        u.x = (u.x > VTH) ? XT.x : fmaf(0.5f, u.x, XT.x);                    \
        u.y = (u.y > VTH) ? XT.y : fmaf(0.5f, u.y, XT.y);                    \
        u.z = (u.z > VTH) ? XT.z : fmaf(0.5f, u.z, XT.z);                    \
        u.w = (u.w > VTH) ? XT.w : fmaf(0.5f, u.w, XT.w);                    \
        o.x = (u.x > VTH) ? BMT.x : 0.0f;                                    \
        o.y = (u.y > VTH) ? BMT.y : 0.0f;                                    \
        o.z = (u.z > VTH) ? BMT.z : 0.0f;                                    \
        o.w = (u.w > VTH) ? BMT.w : 0.0f;                                    \
        out[v + T * VEC_PER_T] = o;                                          \
    }

    {
        const float4 bm0 = bm4[(0 * BS) * PLANE4 + bm_base];
        LIF_BODY(xt0, bm0, 0)
    }
    {
        const float4 bm1 = bm4[(1 * BS) * PLANE4 + bm_base];
        LIF_BODY(xt1, bm1, 1)
    }
    #pragma unroll
    for (int t = 2; t < T_STEPS; ++t) {
        const float4 xt  = x[v + t * VEC_PER_T];
        const float4 bmt = bm4[(t * BS) * PLANE4 + bm_base];
        LIF_BODY(xt, bmt, t)
    }
    #undef LIF_BODY

    // ---- self-reset so graph replays start from a clean state ----
    if (tid == 0) {
        __threadfence();
        const int d = atomicAdd(&d_done, 1);
        if (d == GRID_BLOCKS - 1) {   // everyone is past the spin; safe to reset
            d_flag = 0;
            d_done = 0;
            __threadfence();
        }
    }
}

extern "C" void kernel_launch(void* const* d_in, const int* in_sizes, int n_in,
                              void* d_out, int out_size) {
    const float4* x  = (const float4*)d_in[0];
    const float4* mr = (const float4*)d_in[1];
    float4* out      = (float4*)d_out;

    fused_kernel<<<GRID_BLOCKS, 256>>>(x, mr, out);
}

// round 12
// speedup vs baseline: 1.0005x; 1.0005x over previous
#include <cuda_runtime.h>

// Fixed problem shapes
#define T_STEPS 5
#define BS      32
#define C       64
#define H       64
#define W       64
#define VTH     1.0f
// gamma = DROP_RATE / BLOCK_SIZE^2 = 0.1 / 49
#define GAMMA   0.002040816326530612f

#define PLANE4      1024                      // H*W/4
#define VEC_PER_T   2097152                   // BS*C*H*W/4
#define MAX_SEEDS   256                       // E[k] ~ 4.6 per block region

// ---------------------------------------------------------------------------
// Single fused kernel, NO cross-block dependencies.
// Block = (b, h): owns all 64 channels x 64 w x 5 t for one (batch, row).
// Mask for this row needs only mr[t][b][h-3..h+3][*], t=0..4  (560 float4,
// L2-hot across neighboring blocks). Sparse-seed: gather (t,w) of the ~5
// sub-gamma entries, then keep(t,w) = !(exists seed same t, |pw-w|<=3).
// Then the proven lean LIF body (float mask select), 4 c-groups per thread.
// ---------------------------------------------------------------------------
__global__ void __launch_bounds__(256)
fused_kernel(const float4* __restrict__ x,
             const float4* __restrict__ mr4,
             float4* __restrict__ out) {
    __shared__ int   s_cnt;
    __shared__ int   s_pts[MAX_SEEDS];                    // packed (t << 6) | w
    __shared__ __align__(16) float s_bm[T_STEPS * W];     // keep mask, all t

    const int b   = blockIdx.x >> 6;       // 0..31
    const int h   = blockIdx.x & 63;       // 0..63
    const int tid = threadIdx.x;

    if (tid == 0) s_cnt = 0;
    __syncthreads();

    // ---- gather seeds over 5 t-planes x rows [h-3, h+3] clamped ----
    for (int i = tid; i < T_STEPS * 7 * 16; i += 256) {   // 560 float4
        const int t  = i / 112;
        const int rr = (i % 112) >> 4;
        const int q  = i & 15;
        const int r  = h - 3 + rr;
        if (r >= 0 && r < H) {
            const float4 v = mr4[((t * BS + b) << 10) + (r << 4) + q];
            const int w0 = q << 2;
            if (v.x < GAMMA) { int s = atomicAdd(&s_cnt, 1); if (s < MAX_SEEDS) s_pts[s] = (t << 6) | (w0 + 0); }
            if (v.y < GAMMA) { int s = atomicAdd(&s_cnt, 1); if (s < MAX_SEEDS) s_pts[s] = (t << 6) | (w0 + 1); }
            if (v.z < GAMMA) { int s = atomicAdd(&s_cnt, 1); if (s < MAX_SEEDS) s_pts[s] = (t << 6) | (w0 + 2); }
            if (v.w < GAMMA) { int s = atomicAdd(&s_cnt, 1); if (s < MAX_SEEDS) s_pts[s] = (t << 6) | (w0 + 3); }
        }
    }
    __syncthreads();

    // ---- build keep mask s_bm[t][w] ----
    const int k = (s_cnt < MAX_SEEDS) ? s_cnt : MAX_SEEDS;
    if (tid < T_STEPS * W) {                 // 320 threads... only 256: loop
        // handled below
    }
    for (int j = tid; j < T_STEPS * W; j += 256) {
        const int t = j >> 6;
        const int w = j & 63;
        float keep = 1.0f;
        for (int i = 0; i < k; ++i) {
            const int p = s_pts[i];
            if ((p >> 6) == t) {
                const int d = (p & 63) - w;
                if (d >= -3 && d <= 3) keep = 0.0f;
            }
        }
        s_bm[j] = keep;
    }
    __syncthreads();

    // ---- LIF scan: thread = (c0 = tid>>4, q = tid&15), 4 c-groups ----
    const int q  = tid & 15;
    const int c0 = tid >> 4;                 // 0..15 ; c = c0 + 16*ci
    const float4* __restrict__ bm4s = reinterpret_cast<const float4*>(s_bm);

    float4 u0 = make_float4(0.f, 0.f, 0.f, 0.f);
    float4 u1 = u0, u2 = u0, u3 = u0;

    #pragma unroll
    for (int t = 0; t < T_STEPS; ++t) {
        const float4 bm = bm4s[(t << 4) + q];          // same for all c
        // base float4 index for (t, b, c0, h, q); ci adds 16*1024
        const int baseT = ((((t * BS + b) << 6) + c0) << 10) + (h << 4) + q;

        #define LIF_STEP(U, CI)                                              \
        {                                                                    \
            const int idx = baseT + (CI << 14);                              \
            const float4 xt = __ldcs(&x[idx]);                               \
            U.x = (U.x > VTH) ? xt.x : fmaf(0.5f, U.x, xt.x);                \
            U.y = (U.y > VTH) ? xt.y : fmaf(0.5f, U.y, xt.y);                \
            U.z = (U.z > VTH) ? xt.z : fmaf(0.5f, U.z, xt.z);                \
            U.w = (U.w > VTH) ? xt.w : fmaf(0.5f, U.w, xt.w);                \
            float4 o;                                                        \
            o.x = (U.x > VTH) ? bm.x : 0.0f;                                 \
            o.y = (U.y > VTH) ? bm.y : 0.0f;                                 \
            o.z = (U.z > VTH) ? bm.z : 0.0f;                                 \
            o.w = (U.w > VTH) ? bm.w : 0.0f;                                 \
            __stcs(&out[idx], o);                                            \
        }

        LIF_STEP(u0, 0)
        LIF_STEP(u1, 1)
        LIF_STEP(u2, 2)
        LIF_STEP(u3, 3)
        #undef LIF_STEP
    }
}

extern "C" void kernel_launch(void* const* d_in, const int* in_sizes, int n_in,
                              void* d_out, int out_size) {
    const float4* x  = (const float4*)d_in[0];
    const float4* mr = (const float4*)d_in[1];
    float4* out      = (float4*)d_out;

    fused_kernel<<<BS * H, 256>>>(x, mr, out);   // 2048 blocks
}

// round 13
// speedup vs baseline: 1.1751x; 1.1746x over previous
#include <cuda_runtime.h>

// Fixed problem shapes
#define T_STEPS 5
#define BS      32
#define C       64
#define H       64
#define W       64
#define VTH     1.0f
// gamma = DROP_RATE / BLOCK_SIZE^2 = 0.1 / 49
#define GAMMA   0.002040816326530612f

#define PLANE4      1024                      // H*W/4
#define VEC_PER_T   2097152                   // BS*C*H*W/4
#define MAX_SEEDS   256                       // E[k] ~ 4.6 per (b,h) region

// ---------------------------------------------------------------------------
// Single fused kernel, NO cross-block dependencies, R3-shaped inner body.
// Block = (b, h, cg): 16 channels x 64 w x 5 t for one (batch, row).
//   256 threads = 16 channels x 16 float4 w-quads; ONE float4 site/thread.
// Mask prologue (per block, 4x redundant per (b,h), L2-hot):
//   gather seeds (mr < gamma) from mr[t][b][h-3..h+3][*], t=0..4 (560 float4)
//   -> keep(t,w) = !(exists seed same t with |pw-w| <= 3)  into smem.
// ---------------------------------------------------------------------------
__global__ void __launch_bounds__(256)
fused_kernel(const float4* __restrict__ x,
             const float4* __restrict__ mr4,
             float4* __restrict__ out) {
    __shared__ int   s_cnt;
    __shared__ int   s_pts[MAX_SEEDS];                    // packed (t << 6) | w
    __shared__ __align__(16) float s_bm[T_STEPS * W];     // keep mask, all t

    const int bid = blockIdx.x;
    const int b   = bid >> 8;              // 0..31
    const int h   = (bid >> 2) & 63;       // 0..63
    const int cg  = bid & 3;               // 0..3 (16 channels each)
    const int tid = threadIdx.x;

    if (tid == 0) s_cnt = 0;
    __syncthreads();

    // ---- gather seeds over 5 t-planes x rows [h-3, h+3] clamped ----
    #pragma unroll 1
    for (int i = tid; i < T_STEPS * 7 * 16; i += 256) {   // 560 float4
        const int t  = i / 112;
        const int rr = (i - t * 112) >> 4;
        const int q  = i & 15;
        const int r  = h - 3 + rr;
        if (r >= 0 && r < H) {
            const float4 v = mr4[((t * BS + b) << 10) + (r << 4) + q];
            const int w0 = q << 2;
            if (v.x < GAMMA) { int s = atomicAdd(&s_cnt, 1); if (s < MAX_SEEDS) s_pts[s] = (t << 6) | (w0 + 0); }
            if (v.y < GAMMA) { int s = atomicAdd(&s_cnt, 1); if (s < MAX_SEEDS) s_pts[s] = (t << 6) | (w0 + 1); }
            if (v.z < GAMMA) { int s = atomicAdd(&s_cnt, 1); if (s < MAX_SEEDS) s_pts[s] = (t << 6) | (w0 + 2); }
            if (v.w < GAMMA) { int s = atomicAdd(&s_cnt, 1); if (s < MAX_SEEDS) s_pts[s] = (t << 6) | (w0 + 3); }
        }
    }
    __syncthreads();

    // ---- build keep mask s_bm[t*64 + w] ----
    const int k = (s_cnt < MAX_SEEDS) ? s_cnt : MAX_SEEDS;
    #pragma unroll 1
    for (int j = tid; j < T_STEPS * W; j += 256) {        // 320 entries
        const int t = j >> 6;
        const int w = j & 63;
        float keep = 1.0f;
        for (int i = 0; i < k; ++i) {
            const int p = s_pts[i];
            if ((p >> 6) == t) {
                const int d = (p & 63) - w;
                if (d >= -3 && d <= 3) keep = 0.0f;
            }
        }
        s_bm[j] = keep;
    }
    __syncthreads();

    // ---- LIF scan: one float4 site per thread (R3 body shape) ----
    const int q = tid & 15;
    const int c = (cg << 4) + (tid >> 4);                 // 0..63
    // float4 index of (t=0, b, c, h, q); each t adds VEC_PER_T
    const int base = ((((b << 6) | c) << 6) | h) * 16 + q;
    const float4* __restrict__ bm4s = reinterpret_cast<const float4*>(s_bm);

    float4 u = make_float4(0.f, 0.f, 0.f, 0.f);

    #pragma unroll
    for (int t = 0; t < T_STEPS; ++t) {
        const float4 xt = x[base + t * VEC_PER_T];
        const float4 bm = bm4s[(t << 4) + q];
        float4 o;

        u.x = (u.x > VTH) ? xt.x : fmaf(0.5f, u.x, xt.x);
        u.y = (u.y > VTH) ? xt.y : fmaf(0.5f, u.y, xt.y);
        u.z = (u.z > VTH) ? xt.z : fmaf(0.5f, u.z, xt.z);
        u.w = (u.w > VTH) ? xt.w : fmaf(0.5f, u.w, xt.w);

        o.x = (u.x > VTH) ? bm.x : 0.0f;
        o.y = (u.y > VTH) ? bm.y : 0.0f;
        o.z = (u.z > VTH) ? bm.z : 0.0f;
        o.w = (u.w > VTH) ? bm.w : 0.0f;

        out[base + t * VEC_PER_T] = o;
    }
}

extern "C" void kernel_launch(void* const* d_in, const int* in_sizes, int n_in,
                              void* d_out, int out_size) {
    const float4* x  = (const float4*)d_in[0];
    const float4* mr = (const float4*)d_in[1];
    float4* out      = (float4*)d_out;

    fused_kernel<<<BS * H * 4, 256>>>(x, mr, out);   // 8192 blocks
}